// round 1
// baseline (speedup 1.0000x reference)
#include <cuda_runtime.h>

// DeepSpeed fixed sparse self-attention, B=2, H=16, S=2048, D=64, fp32.
// Layout (head-independent): q-rows [64t,64t+64) attend
//   window keys [64t, 64t+48)           (cols 48..63 of window == stripe m=t)
//   stripe keys [64m+48, 64m+64), m=0..31
// Flash-style streaming softmax over 9 tiles of 64 keys each.

#define SEQ   2048
#define HD    64
#define QT    64
#define PITCH 68          // floats per smem row: 272B = 17*16B, kills stride-64 bank conflicts
#define NEGBIG (-1e30f)

__global__ __launch_bounds__(256, 2)
void sparse_attn_kernel(const float* __restrict__ Q,
                        const float* __restrict__ K,
                        const float* __restrict__ V,
                        float* __restrict__ Out)
{
    extern __shared__ float sm[];
    float* qt = sm;                    // [64][PITCH]  Q^T : qt[d][r]
    float* kt = sm + 64 * PITCH;       // [64][PITCH]  K^T tile : kt[d][c]
    float* vs = sm + 2 * 64 * PITCH;   // [64][PITCH]  V tile   : vs[k][d]
    float* ps = sm + 3 * 64 * PITCH;   // [64][PITCH]  probs    : ps[r][k]

    const int tid = threadIdx.x;
    const int tx  = tid & 15;          // key-col / d-col group (0..15)
    const int ty  = tid >> 4;          // q-row group (0..15)
    const int t   = blockIdx.x;        // q tile (0..31)

    const size_t base = (size_t)blockIdx.y * (size_t)SEQ * HD;   // b*H+h merged
    const float* Qg = Q + base + (size_t)t * QT * HD;
    const float* Kg = K + base;
    const float* Vg = V + base;
    float*       Og = Out + base + (size_t)t * QT * HD;

    // ---- stage Q^T (once per CTA): conflict-free scatter (bank = row) ----
    {
        const int r  = tid & 63;
        const int dc = (tid >> 6) << 4;                 // 0,16,32,48
        const float4* src = reinterpret_cast<const float4*>(Qg + r * HD + dc);
        #pragma unroll
        for (int s = 0; s < 4; s++) {
            float4 f = src[s];
            int d0 = dc + 4 * s;
            qt[(d0 + 0) * PITCH + r] = f.x;
            qt[(d0 + 1) * PITCH + r] = f.y;
            qt[(d0 + 2) * PITCH + r] = f.z;
            qt[(d0 + 3) * PITCH + r] = f.w;
        }
    }

    float m[4], l[4], o[4][4];
    #pragma unroll
    for (int i = 0; i < 4; i++) {
        m[i] = NEGBIG; l[i] = 0.f;
        #pragma unroll
        for (int j = 0; j < 4; j++) o[i][j] = 0.f;
    }

    for (int tile = 0; tile < 9; tile++) {
        __syncthreads();   // previous PV finished reading vs/ps

        // ---- stage K^T tile (gathered keys, transposed) ----
        {
            const int c  = tid & 63;
            const int dc = (tid >> 6) << 4;
            const int gk = (tile == 0) ? (t * 64 + c)
                                       : (((tile - 1) * 4 + (c >> 4)) * 64 + 48 + (c & 15));
            const float4* src = reinterpret_cast<const float4*>(Kg + gk * HD + dc);
            #pragma unroll
            for (int s = 0; s < 4; s++) {
                float4 f = src[s];
                int d0 = dc + 4 * s;
                kt[(d0 + 0) * PITCH + c] = f.x;
                kt[(d0 + 1) * PITCH + c] = f.y;
                kt[(d0 + 2) * PITCH + c] = f.z;
                kt[(d0 + 3) * PITCH + c] = f.w;
            }
        }
        // ---- stage V tile (row-major copy) ----
        {
            const int k  = tid >> 2;                    // 0..63
            const int cb = (tid & 3) << 4;              // 0,16,32,48
            const int gk = (tile == 0) ? (t * 64 + k)
                                       : (((tile - 1) * 4 + (k >> 4)) * 64 + 48 + (k & 15));
            const float4* src = reinterpret_cast<const float4*>(Vg + gk * HD + cb);
            float4*       dst = reinterpret_cast<float4*>(vs + k * PITCH + cb);
            #pragma unroll
            for (int s = 0; s < 4; s++) dst[s] = src[s];
        }
        __syncthreads();

        // ---- S = Q K^T : each thread a 4x4 tile ----
        float acc[4][4];
        #pragma unroll
        for (int i = 0; i < 4; i++)
            #pragma unroll
            for (int j = 0; j < 4; j++) acc[i][j] = 0.f;

        #pragma unroll 8
        for (int d = 0; d < 64; d++) {
            float4 q4 = *reinterpret_cast<const float4*>(qt + d * PITCH + 4 * ty);
            float4 k4 = *reinterpret_cast<const float4*>(kt + d * PITCH + 4 * tx);
            const float qa[4] = {q4.x, q4.y, q4.z, q4.w};
            const float kb[4] = {k4.x, k4.y, k4.z, k4.w};
            #pragma unroll
            for (int i = 0; i < 4; i++)
                #pragma unroll
                for (int j = 0; j < 4; j++)
                    acc[i][j] = fmaf(qa[i], kb[j], acc[i][j]);
        }

        // ---- streaming softmax (rows owned by 16-lane tx groups) ----
        const bool masked = (tile == 0) && (tx >= 12);   // window cols 48..63 counted as stripe m=t
        #pragma unroll
        for (int i = 0; i < 4; i++) {
            float s0[4];
            #pragma unroll
            for (int j = 0; j < 4; j++)
                s0[j] = masked ? NEGBIG : acc[i][j] * 0.125f;   // 64^-0.5

            float rm = fmaxf(fmaxf(s0[0], s0[1]), fmaxf(s0[2], s0[3]));
            #pragma unroll
            for (int off = 8; off >= 1; off >>= 1)
                rm = fmaxf(rm, __shfl_xor_sync(0xffffffffu, rm, off));

            float mn    = fmaxf(m[i], rm);
            float alpha = __expf(m[i] - mn);
            float rs = 0.f;
            #pragma unroll
            for (int j = 0; j < 4; j++) { s0[j] = __expf(s0[j] - mn); rs += s0[j]; }
            #pragma unroll
            for (int off = 8; off >= 1; off >>= 1)
                rs += __shfl_xor_sync(0xffffffffu, rs, off);

            l[i] = l[i] * alpha + rs;
            m[i] = mn;
            #pragma unroll
            for (int j = 0; j < 4; j++) o[i][j] *= alpha;

            *reinterpret_cast<float4*>(ps + (4 * ty + i) * PITCH + 4 * tx) =
                make_float4(s0[0], s0[1], s0[2], s0[3]);
        }
        __syncthreads();   // ps visible

        // ---- O += P V ----
        #pragma unroll 4
        for (int k = 0; k < 64; k++) {
            float4 v4 = *reinterpret_cast<const float4*>(vs + k * PITCH + 4 * tx);
            float pv[4];
            #pragma unroll
            for (int i = 0; i < 4; i++) pv[i] = ps[(4 * ty + i) * PITCH + k];
            #pragma unroll
            for (int i = 0; i < 4; i++) {
                o[i][0] = fmaf(pv[i], v4.x, o[i][0]);
                o[i][1] = fmaf(pv[i], v4.y, o[i][1]);
                o[i][2] = fmaf(pv[i], v4.z, o[i][2]);
                o[i][3] = fmaf(pv[i], v4.w, o[i][3]);
            }
        }
    }

    // ---- epilogue: normalize and store ----
    #pragma unroll
    for (int i = 0; i < 4; i++) {
        float inv = 1.0f / l[i];
        float4 r = make_float4(o[i][0] * inv, o[i][1] * inv, o[i][2] * inv, o[i][3] * inv);
        *reinterpret_cast<float4*>(Og + (4 * ty + i) * HD + 4 * tx) = r;
    }
}

extern "C" void kernel_launch(void* const* d_in, const int* in_sizes, int n_in,
                              void* d_out, int out_size)
{
    const float* Q = (const float*)d_in[0];
    const float* K = (const float*)d_in[1];
    const float* V = (const float*)d_in[2];
    float* O = (float*)d_out;

    const int smem = 4 * 64 * PITCH * (int)sizeof(float);   // 69632 B
    cudaFuncSetAttribute(sparse_attn_kernel,
                         cudaFuncAttributeMaxDynamicSharedMemorySize, smem);

    const int nbh = in_sizes[0] / (SEQ * HD);               // = 32 (b*h merged)
    dim3 grid(SEQ / QT, nbh);
    sparse_attn_kernel<<<grid, 256, smem>>>(Q, K, V, O);
}

// round 3
// speedup vs baseline: 1.1564x; 1.1564x over previous
#include <cuda_runtime.h>
#include <cstdint>

// DeepSpeed fixed sparse self-attention, B=2, H=16, S=2048, D=64, fp32.
// Head-independent layout: q-rows [64t,64t+64) attend
//   window keys [64t, 64t+48)   (cols 48..63 of window tile masked; they equal stripe m=t)
//   stripe keys [64m+48, 64m+64), m=0..31  (8 tiles of 4 stripes)
// Flash softmax over 9 key-tiles of 64.
// Math: mma.sync m16n8k8 tf32 with 3-MMA split-precision compensation
//       (Ah*Bh + Ah*Bl + Al*Bh) -> fp32-equivalent accuracy.

#define SEQ    2048
#define HD     64
#define PITCH  68      // Q/K/P smem pitch (floats)
#define VPITCH 72      // V smem pitch: conflict-free transposed B-frag reads
#define NEGBIG (-1e30f)

__device__ __forceinline__ void mma_tf32(float4& d,
                                         uint32_t a0, uint32_t a1, uint32_t a2, uint32_t a3,
                                         uint32_t b0, uint32_t b1)
{
    asm volatile(
        "mma.sync.aligned.m16n8k8.row.col.f32.tf32.tf32.f32 "
        "{%0,%1,%2,%3}, {%4,%5,%6,%7}, {%8,%9}, {%0,%1,%2,%3};\n"
        : "+f"(d.x), "+f"(d.y), "+f"(d.z), "+f"(d.w)
        : "r"(a0), "r"(a1), "r"(a2), "r"(a3), "r"(b0), "r"(b1));
}

__device__ __forceinline__ uint32_t f2tf(float x)
{
    uint32_t r;
    asm("cvt.rna.tf32.f32 %0, %1;" : "=r"(r) : "f"(x));
    return r;
}

// split x into tf32 hi + tf32 lo (hi + lo == x to ~2^-23 rel)
__device__ __forceinline__ void split_tf(float x, uint32_t& hi, uint32_t& lo)
{
    hi = f2tf(x);
    lo = f2tf(x - __uint_as_float(hi));
}

__global__ __launch_bounds__(128)
void sparse_attn_mma(const float* __restrict__ Q,
                     const float* __restrict__ K,
                     const float* __restrict__ V,
                     float* __restrict__ Out)
{
    extern __shared__ float sm[];
    float* Qs = sm;                   // [64][PITCH]  row-major [q][d]
    float* Ks = Qs + 64 * PITCH;      // [64][PITCH]  row-major [key][d]
    float* Ps = Ks + 64 * PITCH;      // [64][PITCH]  probs [q][key]
    float* Vs = Ps + 64 * PITCH;      // [64][VPITCH] row-major [key][d]

    const int tid  = threadIdx.x;
    const int warp = tid >> 5;
    const int lane = tid & 31;
    const int g    = lane >> 2;       // groupID (row within frag)
    const int q4   = lane & 3;        // threadID-in-group (col within frag)
    const int t    = blockIdx.x;      // q tile 0..31

    const size_t base = (size_t)blockIdx.y * (size_t)SEQ * HD;
    const float* Qg = Q + base + (size_t)t * 64 * HD;
    const float* Kg = K + base;
    const float* Vg = V + base;
    float*       Og = Out + base + (size_t)t * 64 * HD;

    // ---- stage Q (once) ----
    #pragma unroll
    for (int it = 0; it < 8; it++) {
        int idx = tid + it * 128;
        int r = idx >> 4, dc = (idx & 15) << 2;
        float4 f = *reinterpret_cast<const float4*>(Qg + r * HD + dc);
        *reinterpret_cast<float4*>(Qs + r * PITCH + dc) = f;
    }

    // ---- flash state ----
    float4 o[8];
    #pragma unroll
    for (int i = 0; i < 8; i++) o[i] = make_float4(0.f, 0.f, 0.f, 0.f);
    float m0 = NEGBIG, m1 = NEGBIG, l0 = 0.f, l1 = 0.f;

    const int r0 = warp * 16 + g;      // this thread's first q-row

    for (int tile = 0; tile < 9; tile++) {
        __syncthreads();               // prior PV done reading Ks/Vs

        // ---- stage K,V tiles (gathered keys) ----
        #pragma unroll
        for (int it = 0; it < 8; it++) {
            int idx = tid + it * 128;
            int k = idx >> 4, dc = (idx & 15) << 2;
            int gk = (tile == 0) ? (t * 64 + k)
                                 : ((((tile - 1) << 2) + (k >> 4)) * 64 + 48 + (k & 15));
            float4 kf = *reinterpret_cast<const float4*>(Kg + gk * HD + dc);
            *reinterpret_cast<float4*>(Ks + k * PITCH + dc) = kf;
            float4 vf = *reinterpret_cast<const float4*>(Vg + gk * HD + dc);
            *reinterpret_cast<float4*>(Vs + k * VPITCH + dc) = vf;
        }
        __syncthreads();

        // ---- S = Q K^T : 8 n-tiles of 8 keys, split-precision (3 MMAs) ----
        float4 s[8];
        #pragma unroll
        for (int nt = 0; nt < 8; nt++) s[nt] = make_float4(0.f, 0.f, 0.f, 0.f);

        #pragma unroll
        for (int ks = 0; ks < 8; ks++) {
            const int k0 = ks * 8;
            const float* qa = Qs + r0 * PITCH + k0 + q4;
            uint32_t ah[4], al[4];
            split_tf(qa[0],              ah[0], al[0]);
            split_tf(qa[8 * PITCH],      ah[1], al[1]);
            split_tf(qa[4],              ah[2], al[2]);
            split_tf(qa[8 * PITCH + 4],  ah[3], al[3]);
            #pragma unroll
            for (int nt = 0; nt < 8; nt++) {
                const float* kb = Ks + (nt * 8 + g) * PITCH + k0 + q4;
                uint32_t bh0, bl0, bh1, bl1;
                split_tf(kb[0], bh0, bl0);
                split_tf(kb[4], bh1, bl1);
                mma_tf32(s[nt], ah[0], ah[1], ah[2], ah[3], bl0, bl1);
                mma_tf32(s[nt], al[0], al[1], al[2], al[3], bh0, bh1);
                mma_tf32(s[nt], ah[0], ah[1], ah[2], ah[3], bh0, bh1);
            }
        }

        // ---- scale + mask + streaming softmax ----
        const bool t0 = (tile == 0);
        float rm0 = NEGBIG, rm1 = NEGBIG;
        #pragma unroll
        for (int nt = 0; nt < 8; nt++) {
            if (t0 && nt >= 6) {
                s[nt] = make_float4(NEGBIG, NEGBIG, NEGBIG, NEGBIG);
            } else {
                s[nt].x *= 0.125f; s[nt].y *= 0.125f;
                s[nt].z *= 0.125f; s[nt].w *= 0.125f;
            }
            rm0 = fmaxf(rm0, fmaxf(s[nt].x, s[nt].y));
            rm1 = fmaxf(rm1, fmaxf(s[nt].z, s[nt].w));
        }
        rm0 = fmaxf(rm0, __shfl_xor_sync(0xffffffffu, rm0, 1));
        rm0 = fmaxf(rm0, __shfl_xor_sync(0xffffffffu, rm0, 2));
        rm1 = fmaxf(rm1, __shfl_xor_sync(0xffffffffu, rm1, 1));
        rm1 = fmaxf(rm1, __shfl_xor_sync(0xffffffffu, rm1, 2));

        const float mn0 = fmaxf(m0, rm0), mn1 = fmaxf(m1, rm1);
        const float al0 = __expf(m0 - mn0), al1 = __expf(m1 - mn1);
        m0 = mn0; m1 = mn1;

        float rs0 = 0.f, rs1 = 0.f;
        #pragma unroll
        for (int nt = 0; nt < 8; nt++) {
            s[nt].x = __expf(s[nt].x - mn0);
            s[nt].y = __expf(s[nt].y - mn0);
            s[nt].z = __expf(s[nt].z - mn1);
            s[nt].w = __expf(s[nt].w - mn1);
            rs0 += s[nt].x + s[nt].y;
            rs1 += s[nt].z + s[nt].w;
            *reinterpret_cast<float2*>(Ps + r0 * PITCH + nt * 8 + 2 * q4) =
                make_float2(s[nt].x, s[nt].y);
            *reinterpret_cast<float2*>(Ps + (r0 + 8) * PITCH + nt * 8 + 2 * q4) =
                make_float2(s[nt].z, s[nt].w);
        }
        rs0 += __shfl_xor_sync(0xffffffffu, rs0, 1);
        rs0 += __shfl_xor_sync(0xffffffffu, rs0, 2);
        rs1 += __shfl_xor_sync(0xffffffffu, rs1, 1);
        rs1 += __shfl_xor_sync(0xffffffffu, rs1, 2);
        l0 = l0 * al0 + rs0;
        l1 = l1 * al1 + rs1;

        #pragma unroll
        for (int dt = 0; dt < 8; dt++) {
            o[dt].x *= al0; o[dt].y *= al0;
            o[dt].z *= al1; o[dt].w *= al1;
        }
        __syncwarp();   // P visible within warp

        // ---- O += P V : split-precision (3 MMAs) ----
        #pragma unroll
        for (int ks = 0; ks < 8; ks++) {
            const int k0 = ks * 8;
            const float* pa = Ps + r0 * PITCH + k0 + q4;
            uint32_t ah[4], al_[4];
            split_tf(pa[0],              ah[0], al_[0]);
            split_tf(pa[8 * PITCH],      ah[1], al_[1]);
            split_tf(pa[4],              ah[2], al_[2]);
            split_tf(pa[8 * PITCH + 4],  ah[3], al_[3]);
            #pragma unroll
            for (int dt = 0; dt < 8; dt++) {
                const float* vb = Vs + (k0 + q4) * VPITCH + dt * 8 + g;
                uint32_t bh0, bl0, bh1, bl1;
                split_tf(vb[0],          bh0, bl0);
                split_tf(vb[4 * VPITCH], bh1, bl1);
                mma_tf32(o[dt], ah[0], ah[1], ah[2], ah[3], bl0, bl1);
                mma_tf32(o[dt], al_[0], al_[1], al_[2], al_[3], bh0, bh1);
                mma_tf32(o[dt], ah[0], ah[1], ah[2], ah[3], bh0, bh1);
            }
        }
    }

    // ---- epilogue: normalize and store ----
    const float inv0 = 1.f / l0, inv1 = 1.f / l1;
    #pragma unroll
    for (int dt = 0; dt < 8; dt++) {
        *reinterpret_cast<float2*>(Og + r0 * HD + dt * 8 + 2 * q4) =
            make_float2(o[dt].x * inv0, o[dt].y * inv0);
        *reinterpret_cast<float2*>(Og + (r0 + 8) * HD + dt * 8 + 2 * q4) =
            make_float2(o[dt].z * inv1, o[dt].w * inv1);
    }
}

extern "C" void kernel_launch(void* const* d_in, const int* in_sizes, int n_in,
                              void* d_out, int out_size)
{
    const float* Q = (const float*)d_in[0];
    const float* K = (const float*)d_in[1];
    const float* V = (const float*)d_in[2];
    float* O = (float*)d_out;

    const int smem = (3 * 64 * PITCH + 64 * VPITCH) * (int)sizeof(float); // 70656 B
    cudaFuncSetAttribute(sparse_attn_mma,
                         cudaFuncAttributeMaxDynamicSharedMemorySize, smem);

    const int nbh = in_sizes[0] / (SEQ * HD);   // 32 (b*h merged)
    dim3 grid(SEQ / 64, nbh);
    sparse_attn_mma<<<grid, 128, smem>>>(Q, K, V, O);
}

// round 4
// speedup vs baseline: 1.2193x; 1.0544x over previous
#include <cuda_runtime.h>
#include <cstdint>

// DeepSpeed fixed sparse self-attention, B=2, H=16, S=2048, D=64, fp32.
// Head-independent layout: q-rows [64t,64t+64) attend
//   window keys [64t, 64t+48)   (cols 48..63 of window tile masked; they equal stripe m=t)
//   stripe keys [64m+48, 64m+64), m=0..31  (8 tiles of 4 stripes)
// Flash softmax over 9 key-tiles of 64.
// Math: mma.sync m16n8k8 tf32, 3-MMA split compensation (Ah*Bh + Ah*Bl + Al*Bh).
// R4: P buffer aliased onto K buffer (smem 70.7KB -> 53.2KB) => 4 CTAs/SM.

#define SEQ    2048
#define HD     64
#define PITCH  68      // Q/K/P smem pitch (floats): frag reads hit 32 distinct banks
#define VPITCH 72      // V smem pitch: conflict-free transposed B-frag reads
#define NEGBIG (-1e30f)

__device__ __forceinline__ void mma_tf32(float4& d,
                                         uint32_t a0, uint32_t a1, uint32_t a2, uint32_t a3,
                                         uint32_t b0, uint32_t b1)
{
    asm volatile(
        "mma.sync.aligned.m16n8k8.row.col.f32.tf32.tf32.f32 "
        "{%0,%1,%2,%3}, {%4,%5,%6,%7}, {%8,%9}, {%0,%1,%2,%3};\n"
        : "+f"(d.x), "+f"(d.y), "+f"(d.z), "+f"(d.w)
        : "r"(a0), "r"(a1), "r"(a2), "r"(a3), "r"(b0), "r"(b1));
}

__device__ __forceinline__ uint32_t f2tf(float x)
{
    uint32_t r;
    asm("cvt.rna.tf32.f32 %0, %1;" : "=r"(r) : "f"(x));
    return r;
}

__device__ __forceinline__ void split_tf(float x, uint32_t& hi, uint32_t& lo)
{
    hi = f2tf(x);
    lo = f2tf(x - __uint_as_float(hi));
}

__global__ __launch_bounds__(128, 4)
void sparse_attn_mma(const float* __restrict__ Q,
                     const float* __restrict__ K,
                     const float* __restrict__ V,
                     float* __restrict__ Out)
{
    extern __shared__ float sm[];
    float* Qs = sm;                   // [64][PITCH]  row-major [q][d]
    float* Ks = Qs + 64 * PITCH;      // [64][PITCH]  row-major [key][d]; P aliases here
    float* Ps = Ks;                   // probs [q][key]  (ALIAS: valid after QK reads done)
    float* Vs = Ks + 64 * PITCH;      // [64][VPITCH] row-major [key][d]

    const int tid  = threadIdx.x;
    const int warp = tid >> 5;
    const int lane = tid & 31;
    const int g    = lane >> 2;       // groupID (row within frag)
    const int q4   = lane & 3;        // threadID-in-group (col within frag)
    const int t    = blockIdx.x;      // q tile 0..31

    const size_t base = (size_t)blockIdx.y * (size_t)SEQ * HD;
    const float* Qg = Q + base + (size_t)t * 64 * HD;
    const float* Kg = K + base;
    const float* Vg = V + base;
    float*       Og = Out + base + (size_t)t * 64 * HD;

    // ---- stage Q (once) ----
    #pragma unroll
    for (int it = 0; it < 8; it++) {
        int idx = tid + it * 128;
        int r = idx >> 4, dc = (idx & 15) << 2;
        float4 f = *reinterpret_cast<const float4*>(Qg + r * HD + dc);
        *reinterpret_cast<float4*>(Qs + r * PITCH + dc) = f;
    }

    // ---- flash state ----
    float4 o[8];
    #pragma unroll
    for (int i = 0; i < 8; i++) o[i] = make_float4(0.f, 0.f, 0.f, 0.f);
    float m0 = NEGBIG, m1 = NEGBIG, l0 = 0.f, l1 = 0.f;

    const int r0 = warp * 16 + g;      // this thread's first q-row

    for (int tile = 0; tile < 9; tile++) {
        __syncthreads();               // prior PV done reading Ps(=Ks)/Vs

        // ---- stage K,V tiles (gathered keys) ----
        #pragma unroll
        for (int it = 0; it < 8; it++) {
            int idx = tid + it * 128;
            int k = idx >> 4, dc = (idx & 15) << 2;
            int gk = (tile == 0) ? (t * 64 + k)
                                 : ((((tile - 1) << 2) + (k >> 4)) * 64 + 48 + (k & 15));
            float4 kf = *reinterpret_cast<const float4*>(Kg + gk * HD + dc);
            *reinterpret_cast<float4*>(Ks + k * PITCH + dc) = kf;
            float4 vf = *reinterpret_cast<const float4*>(Vg + gk * HD + dc);
            *reinterpret_cast<float4*>(Vs + k * VPITCH + dc) = vf;
        }
        __syncthreads();

        // ---- S = Q K^T : 8 n-tiles of 8 keys, split-precision (3 MMAs) ----
        float4 s[8];
        #pragma unroll
        for (int nt = 0; nt < 8; nt++) s[nt] = make_float4(0.f, 0.f, 0.f, 0.f);

        #pragma unroll
        for (int ks = 0; ks < 8; ks++) {
            const int k0 = ks * 8;
            const float* qa = Qs + r0 * PITCH + k0 + q4;
            uint32_t ah[4], al[4];
            split_tf(qa[0],              ah[0], al[0]);
            split_tf(qa[8 * PITCH],      ah[1], al[1]);
            split_tf(qa[4],              ah[2], al[2]);
            split_tf(qa[8 * PITCH + 4],  ah[3], al[3]);
            #pragma unroll
            for (int nt = 0; nt < 8; nt++) {
                const float* kb = Ks + (nt * 8 + g) * PITCH + k0 + q4;
                uint32_t bh0, bl0, bh1, bl1;
                split_tf(kb[0], bh0, bl0);
                split_tf(kb[4], bh1, bl1);
                mma_tf32(s[nt], ah[0], ah[1], ah[2], ah[3], bl0, bl1);
                mma_tf32(s[nt], al[0], al[1], al[2], al[3], bh0, bh1);
                mma_tf32(s[nt], ah[0], ah[1], ah[2], ah[3], bh0, bh1);
            }
        }

        __syncthreads();   // ALL warps done reading Ks before P overwrites it

        // ---- scale + mask + streaming softmax ----
        const bool t0 = (tile == 0);
        float rm0 = NEGBIG, rm1 = NEGBIG;
        #pragma unroll
        for (int nt = 0; nt < 8; nt++) {
            if (t0 && nt >= 6) {
                s[nt] = make_float4(NEGBIG, NEGBIG, NEGBIG, NEGBIG);
            } else {
                s[nt].x *= 0.125f; s[nt].y *= 0.125f;
                s[nt].z *= 0.125f; s[nt].w *= 0.125f;
            }
            rm0 = fmaxf(rm0, fmaxf(s[nt].x, s[nt].y));
            rm1 = fmaxf(rm1, fmaxf(s[nt].z, s[nt].w));
        }
        rm0 = fmaxf(rm0, __shfl_xor_sync(0xffffffffu, rm0, 1));
        rm0 = fmaxf(rm0, __shfl_xor_sync(0xffffffffu, rm0, 2));
        rm1 = fmaxf(rm1, __shfl_xor_sync(0xffffffffu, rm1, 1));
        rm1 = fmaxf(rm1, __shfl_xor_sync(0xffffffffu, rm1, 2));

        const float mn0 = fmaxf(m0, rm0), mn1 = fmaxf(m1, rm1);
        const float al0 = __expf(m0 - mn0), al1 = __expf(m1 - mn1);
        m0 = mn0; m1 = mn1;

        float rs0 = 0.f, rs1 = 0.f;
        #pragma unroll
        for (int nt = 0; nt < 8; nt++) {
            s[nt].x = __expf(s[nt].x - mn0);
            s[nt].y = __expf(s[nt].y - mn0);
            s[nt].z = __expf(s[nt].z - mn1);
            s[nt].w = __expf(s[nt].w - mn1);
            rs0 += s[nt].x + s[nt].y;
            rs1 += s[nt].z + s[nt].w;
            *reinterpret_cast<float2*>(Ps + r0 * PITCH + nt * 8 + 2 * q4) =
                make_float2(s[nt].x, s[nt].y);
            *reinterpret_cast<float2*>(Ps + (r0 + 8) * PITCH + nt * 8 + 2 * q4) =
                make_float2(s[nt].z, s[nt].w);
        }
        rs0 += __shfl_xor_sync(0xffffffffu, rs0, 1);
        rs0 += __shfl_xor_sync(0xffffffffu, rs0, 2);
        rs1 += __shfl_xor_sync(0xffffffffu, rs1, 1);
        rs1 += __shfl_xor_sync(0xffffffffu, rs1, 2);
        l0 = l0 * al0 + rs0;
        l1 = l1 * al1 + rs1;

        #pragma unroll
        for (int dt = 0; dt < 8; dt++) {
            o[dt].x *= al0; o[dt].y *= al0;
            o[dt].z *= al1; o[dt].w *= al1;
        }
        __syncwarp();   // P visible within warp (PV reads only own warp's rows)

        // ---- O += P V : split-precision (3 MMAs) ----
        #pragma unroll
        for (int ks = 0; ks < 8; ks++) {
            const int k0 = ks * 8;
            const float* pa = Ps + r0 * PITCH + k0 + q4;
            uint32_t ah[4], al_[4];
            split_tf(pa[0],              ah[0], al_[0]);
            split_tf(pa[8 * PITCH],      ah[1], al_[1]);
            split_tf(pa[4],              ah[2], al_[2]);
            split_tf(pa[8 * PITCH + 4],  ah[3], al_[3]);
            #pragma unroll
            for (int dt = 0; dt < 8; dt++) {
                const float* vb = Vs + (k0 + q4) * VPITCH + dt * 8 + g;
                uint32_t bh0, bl0, bh1, bl1;
                split_tf(vb[0],          bh0, bl0);
                split_tf(vb[4 * VPITCH], bh1, bl1);
                mma_tf32(o[dt], ah[0], ah[1], ah[2], ah[3], bl0, bl1);
                mma_tf32(o[dt], al_[0], al_[1], al_[2], al_[3], bh0, bh1);
                mma_tf32(o[dt], ah[0], ah[1], ah[2], ah[3], bh0, bh1);
            }
        }
    }

    // ---- epilogue: normalize and store ----
    const float inv0 = 1.f / l0, inv1 = 1.f / l1;
    #pragma unroll
    for (int dt = 0; dt < 8; dt++) {
        *reinterpret_cast<float2*>(Og + r0 * HD + dt * 8 + 2 * q4) =
            make_float2(o[dt].x * inv0, o[dt].y * inv0);
        *reinterpret_cast<float2*>(Og + (r0 + 8) * HD + dt * 8 + 2 * q4) =
            make_float2(o[dt].z * inv1, o[dt].w * inv1);
    }
}

extern "C" void kernel_launch(void* const* d_in, const int* in_sizes, int n_in,
                              void* d_out, int out_size)
{
    const float* Q = (const float*)d_in[0];
    const float* K = (const float*)d_in[1];
    const float* V = (const float*)d_in[2];
    float* O = (float*)d_out;

    const int smem = (2 * 64 * PITCH + 64 * VPITCH) * (int)sizeof(float); // 53248 B
    cudaFuncSetAttribute(sparse_attn_mma,
                         cudaFuncAttributeMaxDynamicSharedMemorySize, smem);

    const int nbh = in_sizes[0] / (SEQ * HD);   // 32 (b*h merged)
    dim3 grid(SEQ / 64, nbh);
    sparse_attn_mma<<<grid, 128, smem>>>(Q, K, V, O);
}

// round 5
// speedup vs baseline: 3.2278x; 2.6472x over previous
#include <cuda_runtime.h>
#include <cuda_bf16.h>
#include <cstdint>

// DeepSpeed fixed sparse self-attention, B=2, H=16, S=2048, D=64, fp32.
// Head-independent layout: q-rows [64t,64t+64) attend
//   window keys [64t, 64t+48)  (cols 48..63 of window tile masked; equal stripe m=t)
//   stripe keys [64m+48, 64m+64), m=0..31  (8 tiles of 4 stripes)
// Flash softmax over 9 key-tiles of 64.
// Math: mma.sync m16n8k16 bf16, 3-MMA split compensation
//   (Ah*Bl + Al*Bh + Ah*Bh), hi/lo bf16 split done ONCE at staging.
// P stays register-resident (C-frag == A-frag k-pair layout).

#define SEQ    2048
#define HD     64
#define KP     72          // bf16 elements per smem row (36 words) -> conflict-free
#define KPW    36          // words per row
#define NEGBIG (-1e30f)

__device__ __forceinline__ void mma_bf16(float4& d,
                                         uint32_t a0, uint32_t a1, uint32_t a2, uint32_t a3,
                                         uint32_t b0, uint32_t b1)
{
    asm volatile(
        "mma.sync.aligned.m16n8k16.row.col.f32.bf16.bf16.f32 "
        "{%0,%1,%2,%3}, {%4,%5,%6,%7}, {%8,%9}, {%0,%1,%2,%3};\n"
        : "+f"(d.x), "+f"(d.y), "+f"(d.z), "+f"(d.w)
        : "r"(a0), "r"(a1), "r"(a2), "r"(a3), "r"(b0), "r"(b1));
}

__device__ __forceinline__ void ldsm_x2_t(uint32_t& r0, uint32_t& r1, uint32_t addr)
{
    asm volatile("ldmatrix.sync.aligned.m8n8.x2.trans.shared.b16 {%0,%1}, [%2];"
                 : "=r"(r0), "=r"(r1) : "r"(addr));
}

// split pair (a,b) into packed bf16x2 hi word and lo (residual) word
__device__ __forceinline__ void split2(float a, float b, uint32_t& h, uint32_t& l)
{
    __nv_bfloat162 hv = __floats2bfloat162_rn(a, b);   // x=a (low), y=b (high)
    h = *reinterpret_cast<uint32_t*>(&hv);
    float ra = a - __bfloat162float(hv.x);
    float rb = b - __bfloat162float(hv.y);
    __nv_bfloat162 lv = __floats2bfloat162_rn(ra, rb);
    l = *reinterpret_cast<uint32_t*>(&lv);
}

__global__ __launch_bounds__(128, 4)
void sparse_attn_bf16(const float* __restrict__ Q,
                      const float* __restrict__ K,
                      const float* __restrict__ V,
                      float* __restrict__ Out)
{
    extern __shared__ __align__(16) char smraw[];
    __nv_bfloat16* Qh = reinterpret_cast<__nv_bfloat16*>(smraw);   // [64][KP]
    __nv_bfloat16* Ql = Qh + 64 * KP;
    __nv_bfloat16* Kh = Ql + 64 * KP;
    __nv_bfloat16* Kl = Kh + 64 * KP;
    __nv_bfloat16* Vh = Kl + 64 * KP;
    __nv_bfloat16* Vl = Vh + 64 * KP;
    uint32_t* Qh32 = reinterpret_cast<uint32_t*>(Qh);
    uint32_t* Ql32 = reinterpret_cast<uint32_t*>(Ql);
    uint32_t* Kh32 = reinterpret_cast<uint32_t*>(Kh);
    uint32_t* Kl32 = reinterpret_cast<uint32_t*>(Kl);

    const int tid  = threadIdx.x;
    const int warp = tid >> 5;
    const int lane = tid & 31;
    const int g    = lane >> 2;       // groupID (row within frag)
    const int q4   = lane & 3;        // threadID-in-group
    const int t    = blockIdx.x;      // q tile 0..31

    const size_t base = (size_t)blockIdx.y * (size_t)SEQ * HD;
    const float* Qg = Q + base + (size_t)t * 64 * HD;
    const float* Kg = K + base;
    const float* Vg = V + base;
    float*       Og = Out + base + (size_t)t * 64 * HD;

    // ldmatrix base addresses for V (per-lane row pointer, lanes 0..15 used)
    const uint32_t vh_sm = (uint32_t)__cvta_generic_to_shared(Vh) + (lane & 15) * (KP * 2);
    const uint32_t vl_sm = (uint32_t)__cvta_generic_to_shared(Vl) + (lane & 15) * (KP * 2);

    // ---- stage Q hi/lo (once) ----
    #pragma unroll
    for (int it = 0; it < 8; it++) {
        int idx = tid + it * 128;
        int r = idx >> 4, dc = (idx & 15) << 2;
        float4 f = *reinterpret_cast<const float4*>(Qg + r * HD + dc);
        uint32_t h01, l01, h23, l23;
        split2(f.x, f.y, h01, l01);
        split2(f.z, f.w, h23, l23);
        *reinterpret_cast<uint2*>(Qh32 + r * KPW + (dc >> 1)) = make_uint2(h01, h23);
        *reinterpret_cast<uint2*>(Ql32 + r * KPW + (dc >> 1)) = make_uint2(l01, l23);
    }

    // ---- flash state ----
    float4 o[8];
    #pragma unroll
    for (int i = 0; i < 8; i++) o[i] = make_float4(0.f, 0.f, 0.f, 0.f);
    float m0 = NEGBIG, m1 = NEGBIG, l0 = 0.f, l1 = 0.f;

    const int r0 = warp * 16 + g;

    for (int tile = 0; tile < 9; tile++) {
        __syncthreads();   // all warps done reading Kh/Kl/Vh/Vl of prior tile

        // ---- stage K,V (gathered keys), split into bf16 hi/lo once ----
        #pragma unroll
        for (int it = 0; it < 8; it++) {
            int idx = tid + it * 128;
            int k = idx >> 4, dc = (idx & 15) << 2;
            int gk = (tile == 0) ? (t * 64 + k)
                                 : ((((tile - 1) << 2) + (k >> 4)) * 64 + 48 + (k & 15));
            float4 kf = *reinterpret_cast<const float4*>(Kg + gk * HD + dc);
            uint32_t h01, l01, h23, l23;
            split2(kf.x, kf.y, h01, l01);
            split2(kf.z, kf.w, h23, l23);
            *reinterpret_cast<uint2*>(Kh32 + k * KPW + (dc >> 1)) = make_uint2(h01, h23);
            *reinterpret_cast<uint2*>(Kl32 + k * KPW + (dc >> 1)) = make_uint2(l01, l23);

            float4 vf = *reinterpret_cast<const float4*>(Vg + gk * HD + dc);
            split2(vf.x, vf.y, h01, l01);
            split2(vf.z, vf.w, h23, l23);
            *reinterpret_cast<uint2*>(reinterpret_cast<uint32_t*>(Vh) + k * KPW + (dc >> 1)) =
                make_uint2(h01, h23);
            *reinterpret_cast<uint2*>(reinterpret_cast<uint32_t*>(Vl) + k * KPW + (dc >> 1)) =
                make_uint2(l01, l23);
        }
        __syncthreads();

        // ---- S = Q K^T : 4 k-blocks (k16), 8 n-tiles, 3 compensated MMAs ----
        float4 s[8];
        #pragma unroll
        for (int nt = 0; nt < 8; nt++) s[nt] = make_float4(0.f, 0.f, 0.f, 0.f);

        #pragma unroll
        for (int kb = 0; kb < 4; kb++) {
            const int qw = 8 * kb + q4;
            uint32_t ah0 = Qh32[r0 * KPW + qw];
            uint32_t ah1 = Qh32[(r0 + 8) * KPW + qw];
            uint32_t ah2 = Qh32[r0 * KPW + qw + 4];
            uint32_t ah3 = Qh32[(r0 + 8) * KPW + qw + 4];
            uint32_t al0 = Ql32[r0 * KPW + qw];
            uint32_t al1 = Ql32[(r0 + 8) * KPW + qw];
            uint32_t al2 = Ql32[r0 * KPW + qw + 4];
            uint32_t al3 = Ql32[(r0 + 8) * KPW + qw + 4];
            #pragma unroll
            for (int nt = 0; nt < 8; nt++) {
                const int kw = (nt * 8 + g) * KPW + 8 * kb + q4;
                uint32_t bh0 = Kh32[kw], bh1 = Kh32[kw + 4];
                uint32_t bl0 = Kl32[kw], bl1 = Kl32[kw + 4];
                mma_bf16(s[nt], ah0, ah1, ah2, ah3, bl0, bl1);
                mma_bf16(s[nt], al0, al1, al2, al3, bh0, bh1);
                mma_bf16(s[nt], ah0, ah1, ah2, ah3, bh0, bh1);
            }
        }

        // ---- scale + mask + streaming softmax ----
        const bool t0 = (tile == 0);
        float rm0 = NEGBIG, rm1 = NEGBIG;
        #pragma unroll
        for (int nt = 0; nt < 8; nt++) {
            if (t0 && nt >= 6) {
                s[nt] = make_float4(NEGBIG, NEGBIG, NEGBIG, NEGBIG);
            } else {
                s[nt].x *= 0.125f; s[nt].y *= 0.125f;
                s[nt].z *= 0.125f; s[nt].w *= 0.125f;
            }
            rm0 = fmaxf(rm0, fmaxf(s[nt].x, s[nt].y));
            rm1 = fmaxf(rm1, fmaxf(s[nt].z, s[nt].w));
        }
        rm0 = fmaxf(rm0, __shfl_xor_sync(0xffffffffu, rm0, 1));
        rm0 = fmaxf(rm0, __shfl_xor_sync(0xffffffffu, rm0, 2));
        rm1 = fmaxf(rm1, __shfl_xor_sync(0xffffffffu, rm1, 1));
        rm1 = fmaxf(rm1, __shfl_xor_sync(0xffffffffu, rm1, 2));

        const float mn0 = fmaxf(m0, rm0), mn1 = fmaxf(m1, rm1);
        const float alp0 = __expf(m0 - mn0), alp1 = __expf(m1 - mn1);
        m0 = mn0; m1 = mn1;

        float rs0 = 0.f, rs1 = 0.f;
        #pragma unroll
        for (int nt = 0; nt < 8; nt++) {
            s[nt].x = __expf(s[nt].x - mn0);
            s[nt].y = __expf(s[nt].y - mn0);
            s[nt].z = __expf(s[nt].z - mn1);
            s[nt].w = __expf(s[nt].w - mn1);
            rs0 += s[nt].x + s[nt].y;
            rs1 += s[nt].z + s[nt].w;
        }
        rs0 += __shfl_xor_sync(0xffffffffu, rs0, 1);
        rs0 += __shfl_xor_sync(0xffffffffu, rs0, 2);
        rs1 += __shfl_xor_sync(0xffffffffu, rs1, 1);
        rs1 += __shfl_xor_sync(0xffffffffu, rs1, 2);
        l0 = l0 * alp0 + rs0;
        l1 = l1 * alp1 + rs1;

        #pragma unroll
        for (int dt = 0; dt < 8; dt++) {
            o[dt].x *= alp0; o[dt].y *= alp0;
            o[dt].z *= alp1; o[dt].w *= alp1;
        }

        // ---- O += P V : P register-resident (C-frag -> A-frag), V via ldmatrix.trans ----
        #pragma unroll
        for (int kb = 0; kb < 4; kb++) {
            uint32_t ah0, al0_, ah1, al1_, ah2, al2_, ah3, al3_;
            split2(s[2 * kb].x,     s[2 * kb].y,     ah0, al0_);
            split2(s[2 * kb].z,     s[2 * kb].w,     ah1, al1_);
            split2(s[2 * kb + 1].x, s[2 * kb + 1].y, ah2, al2_);
            split2(s[2 * kb + 1].z, s[2 * kb + 1].w, ah3, al3_);
            const uint32_t vhb = vh_sm + kb * (16 * KP * 2);
            const uint32_t vlb = vl_sm + kb * (16 * KP * 2);
            #pragma unroll
            for (int dt = 0; dt < 8; dt++) {
                uint32_t bh0, bh1, bl0, bl1;
                ldsm_x2_t(bh0, bh1, vhb + dt * 16);
                ldsm_x2_t(bl0, bl1, vlb + dt * 16);
                mma_bf16(o[dt], ah0, ah1, ah2, ah3, bl0, bl1);
                mma_bf16(o[dt], al0_, al1_, al2_, al3_, bh0, bh1);
                mma_bf16(o[dt], ah0, ah1, ah2, ah3, bh0, bh1);
            }
        }
    }

    // ---- epilogue: normalize and store ----
    const float inv0 = 1.f / l0, inv1 = 1.f / l1;
    #pragma unroll
    for (int dt = 0; dt < 8; dt++) {
        *reinterpret_cast<float2*>(Og + r0 * HD + dt * 8 + 2 * q4) =
            make_float2(o[dt].x * inv0, o[dt].y * inv0);
        *reinterpret_cast<float2*>(Og + (r0 + 8) * HD + dt * 8 + 2 * q4) =
            make_float2(o[dt].z * inv1, o[dt].w * inv1);
    }
}

extern "C" void kernel_launch(void* const* d_in, const int* in_sizes, int n_in,
                              void* d_out, int out_size)
{
    const float* Q = (const float*)d_in[0];
    const float* K = (const float*)d_in[1];
    const float* V = (const float*)d_in[2];
    float* O = (float*)d_out;

    const int smem = 6 * 64 * KP * 2;   // 55296 B
    cudaFuncSetAttribute(sparse_attn_bf16,
                         cudaFuncAttributeMaxDynamicSharedMemorySize, smem);

    const int nbh = in_sizes[0] / (SEQ * HD);   // 32 (b*h merged)
    dim3 grid(SEQ / 64, nbh);
    sparse_attn_bf16<<<grid, 128, smem>>>(Q, K, V, O);
}

// round 6
// speedup vs baseline: 3.3933x; 1.0513x over previous
#include <cuda_runtime.h>
#include <cuda_bf16.h>
#include <cstdint>

// DeepSpeed fixed sparse self-attention, B=2, H=16, S=2048, D=64, fp32.
// q-rows [64t,64t+64) attend window keys [64t,64t+48) + stripes [64m+48,64m+64).
// Flash softmax; tile0 (window, 48 keys) peeled; tiles 1..8 = 4 stripes each.
// Math: mma.sync m16n8k16 bf16, 3-MMA split compensation (Ah*Bl + Al*Bh + Ah*Bh).
// R6: ldmatrix.x4 fragment loads for Q/K, base-2 softmax, tile-0 peel.

#define SEQ    2048
#define HD     64
#define KP     72          // bf16 elems per smem row (144 B) -> conflict-free ldmatrix
#define KPW    36          // 32-bit words per row
#define NEGBIG (-1e30f)
#define SC2    0.18033688011112042f   // 0.125 * log2(e)

__device__ __forceinline__ void mma_bf16(float4& d,
                                         uint32_t a0, uint32_t a1, uint32_t a2, uint32_t a3,
                                         uint32_t b0, uint32_t b1)
{
    asm volatile(
        "mma.sync.aligned.m16n8k16.row.col.f32.bf16.bf16.f32 "
        "{%0,%1,%2,%3}, {%4,%5,%6,%7}, {%8,%9}, {%0,%1,%2,%3};\n"
        : "+f"(d.x), "+f"(d.y), "+f"(d.z), "+f"(d.w)
        : "r"(a0), "r"(a1), "r"(a2), "r"(a3), "r"(b0), "r"(b1));
}

__device__ __forceinline__ void ldsm_x4(uint32_t& r0, uint32_t& r1, uint32_t& r2, uint32_t& r3,
                                        uint32_t addr)
{
    asm volatile("ldmatrix.sync.aligned.m8n8.x4.shared.b16 {%0,%1,%2,%3}, [%4];"
                 : "=r"(r0), "=r"(r1), "=r"(r2), "=r"(r3) : "r"(addr));
}

__device__ __forceinline__ void ldsm_x2_t(uint32_t& r0, uint32_t& r1, uint32_t addr)
{
    asm volatile("ldmatrix.sync.aligned.m8n8.x2.trans.shared.b16 {%0,%1}, [%2];"
                 : "=r"(r0), "=r"(r1) : "r"(addr));
}

// split pair (a,b) into packed bf16x2 hi word and lo (residual) word
__device__ __forceinline__ void split2(float a, float b, uint32_t& h, uint32_t& l)
{
    __nv_bfloat162 hv = __floats2bfloat162_rn(a, b);
    h = *reinterpret_cast<uint32_t*>(&hv);
    float ra = a - __bfloat162float(hv.x);
    float rb = b - __bfloat162float(hv.y);
    __nv_bfloat162 lv = __floats2bfloat162_rn(ra, rb);
    l = *reinterpret_cast<uint32_t*>(&lv);
}

__global__ __launch_bounds__(128, 4)
void sparse_attn_bf16(const float* __restrict__ Q,
                      const float* __restrict__ K,
                      const float* __restrict__ V,
                      float* __restrict__ Out)
{
    extern __shared__ __align__(16) char smraw[];
    __nv_bfloat16* Qh = reinterpret_cast<__nv_bfloat16*>(smraw);   // [64][KP]
    __nv_bfloat16* Ql = Qh + 64 * KP;
    __nv_bfloat16* Kh = Ql + 64 * KP;
    __nv_bfloat16* Kl = Kh + 64 * KP;
    __nv_bfloat16* Vh = Kl + 64 * KP;
    __nv_bfloat16* Vl = Vh + 64 * KP;
    uint32_t* Qh32 = reinterpret_cast<uint32_t*>(Qh);
    uint32_t* Ql32 = reinterpret_cast<uint32_t*>(Ql);
    uint32_t* Kh32 = reinterpret_cast<uint32_t*>(Kh);
    uint32_t* Kl32 = reinterpret_cast<uint32_t*>(Kl);
    uint32_t* Vh32 = reinterpret_cast<uint32_t*>(Vh);
    uint32_t* Vl32 = reinterpret_cast<uint32_t*>(Vl);

    const int tid  = threadIdx.x;
    const int warp = tid >> 5;
    const int lane = tid & 31;
    const int g    = lane >> 2;
    const int q4   = lane & 3;
    const int t    = blockIdx.x;

    const size_t base = (size_t)blockIdx.y * (size_t)SEQ * HD;
    const float* Qg = Q + base + (size_t)t * 64 * HD;
    const float* Kg = K + base;
    const float* Vg = V + base;
    float*       Og = Out + base + (size_t)t * 64 * HD;

    // ldmatrix per-lane source offsets (bytes)
    const uint32_t qh_sm = (uint32_t)__cvta_generic_to_shared(Qh);
    const uint32_t ql_sm = (uint32_t)__cvta_generic_to_shared(Ql);
    const uint32_t kh_sm = (uint32_t)__cvta_generic_to_shared(Kh);
    const uint32_t kl_sm = (uint32_t)__cvta_generic_to_shared(Kl);
    // A-frag x4: rows warp*16 + (lane>>3 &1)*8 + lane&7 ; col half lane>>4
    const uint32_t qoff = (warp * 16 + ((lane >> 3) & 1) * 8 + (lane & 7)) * (KP * 2)
                        + (lane >> 4) * 16;
    // B-frag x4 (2 n-tiles): rows (lane>>4)*8 + lane&7 ; col half (lane>>3)&1
    const uint32_t koff = ((lane >> 4) * 8 + (lane & 7)) * (KP * 2)
                        + ((lane >> 3) & 1) * 16;
    const uint32_t vh_sm = (uint32_t)__cvta_generic_to_shared(Vh) + (lane & 15) * (KP * 2);
    const uint32_t vl_sm = (uint32_t)__cvta_generic_to_shared(Vl) + (lane & 15) * (KP * 2);

    // ---- stage Q hi/lo (once) ----
    #pragma unroll
    for (int it = 0; it < 8; it++) {
        int idx = tid + it * 128;
        int r = idx >> 4, dc = (idx & 15) << 2;
        float4 f = *reinterpret_cast<const float4*>(Qg + r * HD + dc);
        uint32_t h01, l01, h23, l23;
        split2(f.x, f.y, h01, l01);
        split2(f.z, f.w, h23, l23);
        *reinterpret_cast<uint2*>(Qh32 + r * KPW + (dc >> 1)) = make_uint2(h01, h23);
        *reinterpret_cast<uint2*>(Ql32 + r * KPW + (dc >> 1)) = make_uint2(l01, l23);
    }

    float4 o[8];
    #pragma unroll
    for (int i = 0; i < 8; i++) o[i] = make_float4(0.f, 0.f, 0.f, 0.f);
    float m0, m1, l0, l1;
    const int r0 = warp * 16 + g;

    // ================= tile 0: window (48 valid keys, nt 0..5) =================
    {
        #pragma unroll
        for (int it = 0; it < 8; it++) {
            int idx = tid + it * 128;
            int k = idx >> 4, dc = (idx & 15) << 2;
            int gk = t * 64 + k;
            float4 kf = *reinterpret_cast<const float4*>(Kg + gk * HD + dc);
            uint32_t h01, l01, h23, l23;
            split2(kf.x, kf.y, h01, l01);
            split2(kf.z, kf.w, h23, l23);
            *reinterpret_cast<uint2*>(Kh32 + k * KPW + (dc >> 1)) = make_uint2(h01, h23);
            *reinterpret_cast<uint2*>(Kl32 + k * KPW + (dc >> 1)) = make_uint2(l01, l23);
            float4 vf = *reinterpret_cast<const float4*>(Vg + gk * HD + dc);
            split2(vf.x, vf.y, h01, l01);
            split2(vf.z, vf.w, h23, l23);
            *reinterpret_cast<uint2*>(Vh32 + k * KPW + (dc >> 1)) = make_uint2(h01, h23);
            *reinterpret_cast<uint2*>(Vl32 + k * KPW + (dc >> 1)) = make_uint2(l01, l23);
        }
        __syncthreads();

        float4 s[6];
        #pragma unroll
        for (int nt = 0; nt < 6; nt++) s[nt] = make_float4(0.f, 0.f, 0.f, 0.f);

        #pragma unroll
        for (int kb = 0; kb < 4; kb++) {
            uint32_t ah0, ah1, ah2, ah3, al0, al1, al2, al3;
            ldsm_x4(ah0, ah1, ah2, ah3, qh_sm + qoff + kb * 32);
            ldsm_x4(al0, al1, al2, al3, ql_sm + qoff + kb * 32);
            #pragma unroll
            for (int ntp = 0; ntp < 3; ntp++) {
                uint32_t bh0, bh1, bh2, bh3, bl0, bl1, bl2, bl3;
                ldsm_x4(bh0, bh1, bh2, bh3, kh_sm + koff + ntp * (16 * KP * 2) + kb * 32);
                ldsm_x4(bl0, bl1, bl2, bl3, kl_sm + koff + ntp * (16 * KP * 2) + kb * 32);
                mma_bf16(s[2 * ntp],     ah0, ah1, ah2, ah3, bl0, bl1);
                mma_bf16(s[2 * ntp],     al0, al1, al2, al3, bh0, bh1);
                mma_bf16(s[2 * ntp],     ah0, ah1, ah2, ah3, bh0, bh1);
                mma_bf16(s[2 * ntp + 1], ah0, ah1, ah2, ah3, bl2, bl3);
                mma_bf16(s[2 * ntp + 1], al0, al1, al2, al3, bh2, bh3);
                mma_bf16(s[2 * ntp + 1], ah0, ah1, ah2, ah3, bh2, bh3);
            }
        }

        float rm0 = NEGBIG, rm1 = NEGBIG;
        #pragma unroll
        for (int nt = 0; nt < 6; nt++) {
            s[nt].x *= SC2; s[nt].y *= SC2; s[nt].z *= SC2; s[nt].w *= SC2;
            rm0 = fmaxf(rm0, fmaxf(s[nt].x, s[nt].y));
            rm1 = fmaxf(rm1, fmaxf(s[nt].z, s[nt].w));
        }
        rm0 = fmaxf(rm0, __shfl_xor_sync(0xffffffffu, rm0, 1));
        rm0 = fmaxf(rm0, __shfl_xor_sync(0xffffffffu, rm0, 2));
        rm1 = fmaxf(rm1, __shfl_xor_sync(0xffffffffu, rm1, 1));
        rm1 = fmaxf(rm1, __shfl_xor_sync(0xffffffffu, rm1, 2));
        m0 = rm0; m1 = rm1;

        float rs0 = 0.f, rs1 = 0.f;
        #pragma unroll
        for (int nt = 0; nt < 6; nt++) {
            s[nt].x = exp2f(s[nt].x - m0);
            s[nt].y = exp2f(s[nt].y - m0);
            s[nt].z = exp2f(s[nt].z - m1);
            s[nt].w = exp2f(s[nt].w - m1);
            rs0 += s[nt].x + s[nt].y;
            rs1 += s[nt].z + s[nt].w;
        }
        rs0 += __shfl_xor_sync(0xffffffffu, rs0, 1);
        rs0 += __shfl_xor_sync(0xffffffffu, rs0, 2);
        rs1 += __shfl_xor_sync(0xffffffffu, rs1, 1);
        rs1 += __shfl_xor_sync(0xffffffffu, rs1, 2);
        l0 = rs0; l1 = rs1;

        #pragma unroll
        for (int kb = 0; kb < 3; kb++) {
            uint32_t ah0, al0_, ah1, al1_, ah2, al2_, ah3, al3_;
            split2(s[2 * kb].x,     s[2 * kb].y,     ah0, al0_);
            split2(s[2 * kb].z,     s[2 * kb].w,     ah1, al1_);
            split2(s[2 * kb + 1].x, s[2 * kb + 1].y, ah2, al2_);
            split2(s[2 * kb + 1].z, s[2 * kb + 1].w, ah3, al3_);
            const uint32_t vhb = vh_sm + kb * (16 * KP * 2);
            const uint32_t vlb = vl_sm + kb * (16 * KP * 2);
            #pragma unroll
            for (int dt = 0; dt < 8; dt++) {
                uint32_t bh0, bh1, bl0, bl1;
                ldsm_x2_t(bh0, bh1, vhb + dt * 16);
                ldsm_x2_t(bl0, bl1, vlb + dt * 16);
                mma_bf16(o[dt], ah0, ah1, ah2, ah3, bl0, bl1);
                mma_bf16(o[dt], al0_, al1_, al2_, al3_, bh0, bh1);
                mma_bf16(o[dt], ah0, ah1, ah2, ah3, bh0, bh1);
            }
        }
    }

    // ================= tiles 1..8: 4 stripes of 16 keys each =================
    for (int tile = 1; tile < 9; tile++) {
        __syncthreads();

        #pragma unroll
        for (int it = 0; it < 8; it++) {
            int idx = tid + it * 128;
            int k = idx >> 4, dc = (idx & 15) << 2;
            int gk = (((tile - 1) << 2) + (k >> 4)) * 64 + 48 + (k & 15);
            float4 kf = *reinterpret_cast<const float4*>(Kg + gk * HD + dc);
            uint32_t h01, l01, h23, l23;
            split2(kf.x, kf.y, h01, l01);
            split2(kf.z, kf.w, h23, l23);
            *reinterpret_cast<uint2*>(Kh32 + k * KPW + (dc >> 1)) = make_uint2(h01, h23);
            *reinterpret_cast<uint2*>(Kl32 + k * KPW + (dc >> 1)) = make_uint2(l01, l23);
            float4 vf = *reinterpret_cast<const float4*>(Vg + gk * HD + dc);
            split2(vf.x, vf.y, h01, l01);
            split2(vf.z, vf.w, h23, l23);
            *reinterpret_cast<uint2*>(Vh32 + k * KPW + (dc >> 1)) = make_uint2(h01, h23);
            *reinterpret_cast<uint2*>(Vl32 + k * KPW + (dc >> 1)) = make_uint2(l01, l23);
        }
        __syncthreads();

        float4 s[8];
        #pragma unroll
        for (int nt = 0; nt < 8; nt++) s[nt] = make_float4(0.f, 0.f, 0.f, 0.f);

        #pragma unroll
        for (int kb = 0; kb < 4; kb++) {
            uint32_t ah0, ah1, ah2, ah3, al0, al1, al2, al3;
            ldsm_x4(ah0, ah1, ah2, ah3, qh_sm + qoff + kb * 32);
            ldsm_x4(al0, al1, al2, al3, ql_sm + qoff + kb * 32);
            #pragma unroll
            for (int ntp = 0; ntp < 4; ntp++) {
                uint32_t bh0, bh1, bh2, bh3, bl0, bl1, bl2, bl3;
                ldsm_x4(bh0, bh1, bh2, bh3, kh_sm + koff + ntp * (16 * KP * 2) + kb * 32);
                ldsm_x4(bl0, bl1, bl2, bl3, kl_sm + koff + ntp * (16 * KP * 2) + kb * 32);
                mma_bf16(s[2 * ntp],     ah0, ah1, ah2, ah3, bl0, bl1);
                mma_bf16(s[2 * ntp],     al0, al1, al2, al3, bh0, bh1);
                mma_bf16(s[2 * ntp],     ah0, ah1, ah2, ah3, bh0, bh1);
                mma_bf16(s[2 * ntp + 1], ah0, ah1, ah2, ah3, bl2, bl3);
                mma_bf16(s[2 * ntp + 1], al0, al1, al2, al3, bh2, bh3);
                mma_bf16(s[2 * ntp + 1], ah0, ah1, ah2, ah3, bh2, bh3);
            }
        }

        float rm0 = NEGBIG, rm1 = NEGBIG;
        #pragma unroll
        for (int nt = 0; nt < 8; nt++) {
            s[nt].x *= SC2; s[nt].y *= SC2; s[nt].z *= SC2; s[nt].w *= SC2;
            rm0 = fmaxf(rm0, fmaxf(s[nt].x, s[nt].y));
            rm1 = fmaxf(rm1, fmaxf(s[nt].z, s[nt].w));
        }
        rm0 = fmaxf(rm0, __shfl_xor_sync(0xffffffffu, rm0, 1));
        rm0 = fmaxf(rm0, __shfl_xor_sync(0xffffffffu, rm0, 2));
        rm1 = fmaxf(rm1, __shfl_xor_sync(0xffffffffu, rm1, 1));
        rm1 = fmaxf(rm1, __shfl_xor_sync(0xffffffffu, rm1, 2));

        const float mn0 = fmaxf(m0, rm0), mn1 = fmaxf(m1, rm1);
        const float alp0 = exp2f(m0 - mn0), alp1 = exp2f(m1 - mn1);
        m0 = mn0; m1 = mn1;

        float rs0 = 0.f, rs1 = 0.f;
        #pragma unroll
        for (int nt = 0; nt < 8; nt++) {
            s[nt].x = exp2f(s[nt].x - mn0);
            s[nt].y = exp2f(s[nt].y - mn0);
            s[nt].z = exp2f(s[nt].z - mn1);
            s[nt].w = exp2f(s[nt].w - mn1);
            rs0 += s[nt].x + s[nt].y;
            rs1 += s[nt].z + s[nt].w;
        }
        rs0 += __shfl_xor_sync(0xffffffffu, rs0, 1);
        rs0 += __shfl_xor_sync(0xffffffffu, rs0, 2);
        rs1 += __shfl_xor_sync(0xffffffffu, rs1, 1);
        rs1 += __shfl_xor_sync(0xffffffffu, rs1, 2);
        l0 = l0 * alp0 + rs0;
        l1 = l1 * alp1 + rs1;

        #pragma unroll
        for (int dt = 0; dt < 8; dt++) {
            o[dt].x *= alp0; o[dt].y *= alp0;
            o[dt].z *= alp1; o[dt].w *= alp1;
        }

        #pragma unroll
        for (int kb = 0; kb < 4; kb++) {
            uint32_t ah0, al0_, ah1, al1_, ah2, al2_, ah3, al3_;
            split2(s[2 * kb].x,     s[2 * kb].y,     ah0, al0_);
            split2(s[2 * kb].z,     s[2 * kb].w,     ah1, al1_);
            split2(s[2 * kb + 1].x, s[2 * kb + 1].y, ah2, al2_);
            split2(s[2 * kb + 1].z, s[2 * kb + 1].w, ah3, al3_);
            const uint32_t vhb = vh_sm + kb * (16 * KP * 2);
            const uint32_t vlb = vl_sm + kb * (16 * KP * 2);
            #pragma unroll
            for (int dt = 0; dt < 8; dt++) {
                uint32_t bh0, bh1, bl0, bl1;
                ldsm_x2_t(bh0, bh1, vhb + dt * 16);
                ldsm_x2_t(bl0, bl1, vlb + dt * 16);
                mma_bf16(o[dt], ah0, ah1, ah2, ah3, bl0, bl1);
                mma_bf16(o[dt], al0_, al1_, al2_, al3_, bh0, bh1);
                mma_bf16(o[dt], ah0, ah1, ah2, ah3, bh0, bh1);
            }
        }
    }

    // ---- epilogue ----
    const float inv0 = 1.f / l0, inv1 = 1.f / l1;
    #pragma unroll
    for (int dt = 0; dt < 8; dt++) {
        *reinterpret_cast<float2*>(Og + r0 * HD + dt * 8 + 2 * q4) =
            make_float2(o[dt].x * inv0, o[dt].y * inv0);
        *reinterpret_cast<float2*>(Og + (r0 + 8) * HD + dt * 8 + 2 * q4) =
            make_float2(o[dt].z * inv1, o[dt].w * inv1);
    }
}

extern "C" void kernel_launch(void* const* d_in, const int* in_sizes, int n_in,
                              void* d_out, int out_size)
{
    const float* Q = (const float*)d_in[0];
    const float* K = (const float*)d_in[1];
    const float* V = (const float*)d_in[2];
    float* O = (float*)d_out;

    const int smem = 6 * 64 * KP * 2;   // 55296 B
    cudaFuncSetAttribute(sparse_attn_bf16,
                         cudaFuncAttributeMaxDynamicSharedMemorySize, smem);

    const int nbh = in_sizes[0] / (SEQ * HD);   // 32 (b*h merged)
    dim3 grid(SEQ / 64, nbh);
    sparse_attn_bf16<<<grid, 128, smem>>>(Q, K, V, O);
}